// round 9
// baseline (speedup 1.0000x reference)
#include <cuda_runtime.h>
#include <cuda_bf16.h>
#include <cstdint>

// ============================================================================
// TestRNN: B=64, T=2048, D=256, V=256
//   K1 tables: WxE = E@Wx^T, GE = sigmoid(E@Wz^T)  (V=256 collapse)
//             + resets progress counters for graph replay determinism
//   K2 recurrence: EXACT Round-6 measured version (64 chains, 2-CTA clusters,
//      bulk h-half exchange) + PDL trigger after step 0 + per-rank progress
//      counters published every 128 steps.
//   K3 head: out = y @ E^T. Launched with programmatic stream serialization:
//      starts on idle SMs DURING K2, each CTA polls progress for its tile.
//      If PDL is inactive anywhere, polls pass instantly -> plain serial run.
// ============================================================================

#define RB 64
#define RT 2048
#define RD 256
#define RV 256

__device__ float g_y[RB * RT * RD];       // 128 MB scratch
__device__ float g_WxE[RV * RD];
__device__ float g_GE[RV * RD];
__device__ int g_progA[RB];               // rank-0 half progress per chain
__device__ int g_progB[RB];               // rank-1 half progress per chain

// ---------------------------------------------------------------------------
__device__ __forceinline__ void fma2(unsigned long long& c,
                                     unsigned long long a,
                                     unsigned long long b) {
    asm("fma.rn.f32x2 %0, %1, %2, %0;" : "+l"(c) : "l"(a), "l"(b));
}
__device__ __forceinline__ unsigned long long pack2(float x, float y) {
    unsigned long long r;
    asm("mov.b64 %0, {%1, %2};" : "=l"(r) : "f"(x), "f"(y));
    return r;
}
__device__ __forceinline__ float2 unpack2(unsigned long long v) {
    float2 f;
    asm("mov.b64 {%0, %1}, %2;" : "=f"(f.x), "=f"(f.y) : "l"(v));
    return f;
}
__device__ __forceinline__ float tanh_fast(float x) {
    float xc = fminf(fmaxf(x, -15.0f), 15.0f);
    float e2 = __expf(2.0f * xc);
    return __fdividef(e2 - 1.0f, e2 + 1.0f);
}
__device__ __forceinline__ uint32_t smem_u32(const void* p) {
    uint32_t a;
    asm("{ .reg .u64 t; cvta.to.shared.u64 t, %1; cvt.u32.u64 %0, t; }"
        : "=r"(a) : "l"(p));
    return a;
}
__device__ __forceinline__ uint32_t ctarank() {
    uint32_t r;
    asm("mov.u32 %0, %%cluster_ctarank;" : "=r"(r));
    return r;
}
__device__ __forceinline__ uint32_t mapa_u32(uint32_t laddr, uint32_t rank) {
    uint32_t r;
    asm("mapa.shared::cluster.u32 %0, %1, %2;" : "=r"(r) : "r"(laddr), "r"(rank));
    return r;
}
__device__ __forceinline__ void bulk_copy_to_peer(uint32_t dst_cluster,
                                                  uint32_t src_cta,
                                                  uint32_t bytes,
                                                  uint32_t rbar_cluster) {
    asm volatile(
        "cp.async.bulk.shared::cluster.shared::cta.mbarrier::complete_tx::bytes "
        "[%0], [%1], %2, [%3];"
        :: "r"(dst_cluster), "r"(src_cta), "r"(bytes), "r"(rbar_cluster)
        : "memory");
}
__device__ __forceinline__ void fence_proxy_async_cta() {
    asm volatile("fence.proxy.async.shared::cta;" ::: "memory");
}
__device__ __forceinline__ void mbar_init(uint32_t addr, uint32_t cnt) {
    asm volatile("mbarrier.init.shared.b64 [%0], %1;" :: "r"(addr), "r"(cnt) : "memory");
}
__device__ __forceinline__ void mbar_expect_tx(uint32_t addr, uint32_t bytes) {
    asm volatile("mbarrier.arrive.expect_tx.shared.b64 _, [%0], %1;"
                 :: "r"(addr), "r"(bytes) : "memory");
}
__device__ __forceinline__ void mbar_wait_acq_cluster(uint32_t addr, uint32_t parity) {
    asm volatile(
        "{\n\t"
        ".reg .pred P1;\n\t"
        "WAIT_LOOP_%=:\n\t"
        "mbarrier.try_wait.parity.acquire.cluster.shared::cta.b64 P1, [%0], %1, 0x989680;\n\t"
        "@P1 bra.uni WAIT_DONE_%=;\n\t"
        "bra.uni WAIT_LOOP_%=;\n\t"
        "WAIT_DONE_%=:\n\t"
        "}"
        :: "r"(addr), "r"(parity) : "memory");
}
#define CLUSTER_SYNC_() do {                                          \
    asm volatile("barrier.cluster.arrive.aligned;" ::: "memory");     \
    asm volatile("barrier.cluster.wait.aligned;" ::: "memory");       \
} while (0)

// ============================================================================
// K1: tables (+ progress reset for deterministic graph replays)
// ============================================================================
__global__ void rnn_tables_kernel(const float* __restrict__ E,
                                  const float* __restrict__ Wx,
                                  const float* __restrict__ Wz) {
    __shared__ float Ev[RD];
    const int v = blockIdx.x;
    const int e = threadIdx.x;
    if (v == 0 && e < RB) {
        g_progA[e] = 0;
        g_progB[e] = 0;
    }
    Ev[e] = E[v * RD + e];
    __syncthreads();

    const float4* wx4 = (const float4*)(Wx + (size_t)e * RD);
    const float4* wz4 = (const float4*)(Wz + (size_t)e * RD);
    const float4* ev4 = (const float4*)Ev;

    float ax = 0.f, az = 0.f;
#pragma unroll 8
    for (int i = 0; i < RD / 4; i++) {
        float4 ev = ev4[i];
        float4 a = wx4[i];
        float4 b = wz4[i];
        ax += ev.x * a.x + ev.y * a.y + ev.z * a.z + ev.w * a.w;
        az += ev.x * b.x + ev.y * b.y + ev.z * b.z + ev.w * b.w;
    }
    g_WxE[v * RD + e] = ax;
    g_GE[v * RD + e] = __fdividef(1.0f, 1.0f + __expf(-az));
}

// ============================================================================
// K2: recurrence — EXACT Round-6 measured structure (bulk h-half exchange)
//     + PDL trigger + progress publication.
// ============================================================================
__global__ __launch_bounds__(512, 1) __cluster_dims__(2, 1, 1)
void rnn_recurrence_kernel(const int* __restrict__ tokens,
                           const float* __restrict__ Wh) {
    __shared__ __align__(16) float h_loc[2][128];   // local half (bulk src)
    __shared__ __align__(16) float h_peer[2][128];  // peer half (bulk dst)
    __shared__ float red[2][128];
    __shared__ int toks[RT];
    __shared__ __align__(8) unsigned long long bar;

    const int tid = threadIdx.x;
    const int warp = tid >> 5;
    const int lane = tid & 31;
    const int g = warp >> 3;
    const int eo = (warp & 7) * 16 + (lane >> 1);
    const int sub = lane & 1;
    const uint32_t r = ctarank();
    const uint32_t peer = r ^ 1u;
    const int b = blockIdx.x >> 1;
    const int e = (int)r * 128 + eo;
    const int half_base = (g == 0) ? (int)r * 128 : (int)peer * 128;

    // ---- weights: Wh[e][half_base + sub*64 .. +63] in 32 f32x2 regs ----
    unsigned long long w[32];
    {
        const unsigned long long* wr =
            (const unsigned long long*)(Wh + (size_t)e * RD + half_base + sub * 64);
#pragma unroll
        for (int i = 0; i < 32; i++) w[i] = wr[i];
    }

    for (int idx = tid; idx < RT; idx += 512)
        toks[idx] = tokens[(size_t)b * RT + idx];

    if (tid < 128) h_loc[0][tid] = 0.0f;
    else if (tid < 256) h_peer[0][tid - 128] = 0.0f;
    if (tid == 0) mbar_init(smem_u32(&bar), 1);
    __syncthreads();
    CLUSTER_SYNC_();

    const uint32_t loc_hloc = smem_u32(&h_loc[0][0]);
    const uint32_t rem_hpeer = mapa_u32(smem_u32(&h_peer[0][0]), peer);
    const uint32_t rem_bar = mapa_u32(smem_u32(&bar), peer);
    const uint32_t loc_bar = smem_u32(&bar);

    float* ybase = g_y + (size_t)b * RT * RD;
    int* myprog = (r == 0) ? &g_progA[b] : &g_progB[b];

    float wx = 0.f, gv = 0.f;
    if (g == 0) {
        wx = g_WxE[toks[0] * RD + e];
        gv = g_GE[toks[0] * RD + e];
    }

    const float* hb_base = (g == 0) ? &h_loc[0][0] : &h_peer[0][0];
    uint32_t parity = 0;

    for (int t = 0; t < RT; t++) {
        const int cur = t & 1;
        const int nxt = cur ^ 1;

        if (g == 1) {
            if (t > 0) {
                mbar_wait_acq_cluster(loc_bar, parity);
                parity ^= 1;
            }
            if (tid == 256 && t + 1 < RT)
                mbar_expect_tx(loc_bar, 512u);   // arm next phase (post-wait)
        }

        // ---- 64-d partial dot ----
        const float* hb = hb_base + cur * 128 + sub * 64;
        unsigned long long a0 = 0ull, a1 = 0ull, a2 = 0ull, a3 = 0ull;
#pragma unroll
        for (int i = 0; i < 8; i++) {
            ulonglong2 ha = *(const ulonglong2*)(hb + 8 * i);
            ulonglong2 hc = *(const ulonglong2*)(hb + 8 * i + 4);
            fma2(a0, w[4 * i + 0], ha.x);
            fma2(a1, w[4 * i + 1], ha.y);
            fma2(a2, w[4 * i + 2], hc.x);
            fma2(a3, w[4 * i + 3], hc.y);
        }
        float2 s0 = unpack2(a0), s1 = unpack2(a1);
        float2 s2 = unpack2(a2), s3 = unpack2(a3);
        float partial = ((s0.x + s0.y) + (s1.x + s1.y)) +
                        ((s2.x + s2.y) + (s3.x + s3.y));
        partial += __shfl_xor_sync(0xffffffffu, partial, 1);

        if (g == 1 && sub == 0) red[cur][eo] = partial;

        __syncthreads();   // red[cur] visible to g0

        if (g == 0) {
            if (sub == 0) {
                float tot = partial + red[cur][eo] + wx;
                float hn = tanh_fast(tot);
                ybase[(size_t)t * RD + e] = hn * gv;
                h_loc[nxt][eo] = hn;
                // milestone: make this CTA's y stores (<= t) GPU-visible
                if ((t & 127) == 127) __threadfence();
            }
            if (t + 1 < RT) {   // prefetch next tables (overlaps delivery)
                int tk = toks[t + 1];
                wx = g_WxE[tk * RD + e];
                gv = g_GE[tk * RD + e];
            }
            asm volatile("bar.sync 1, 256;" ::: "memory");  // h_loc[nxt] done
            if (tid == 0 && t + 1 < RT) {
                fence_proxy_async_cta();  // order generic STS before bulk read
                bulk_copy_to_peer(rem_hpeer + (uint32_t)nxt * 512u,
                                  loc_hloc + (uint32_t)nxt * 512u,
                                  512u, rem_bar);
            }
        }

        __syncthreads();  // h_loc[nxt] visible; buffers safely double-phased

        // publish progress (all writers fenced + synced above)
        if (tid == 0 && (t & 127) == 127) {
            __threadfence();
            *(volatile int*)myprog = t + 1;
        }
        // let the dependent K3 grid launch onto idle SMs
        if (t == 0)
            asm volatile("griddepcontrol.launch_dependents;" ::: "memory");
    }

    CLUSTER_SYNC_();
}

// ============================================================================
// K3: head GEMM  out[m][v] = sum_d y[m][d] * E[v][d]
// Flat grid 2048, t-chunk-major block order. Each CTA gates on progress.
// ============================================================================
#define HBK 32

__global__ __launch_bounds__(256, 2)
void rnn_head_kernel(const float* __restrict__ E,
                     float* __restrict__ out) {
    __shared__ float As[HBK][128];
    __shared__ float Bs[HBK][128];

    const int bid = blockIdx.x;
    const int tc = bid >> 7;           // 0..15 (t-chunk)
    const int b = (bid >> 1) & 63;     // chain
    const int nh = bid & 1;            // vocab half
    const int m0 = b * RT + tc * 128;
    const int n0 = nh * 128;

    // PDL gate: ensures K1's counter reset (pre-primary) is visible
    asm volatile("griddepcontrol.wait;" ::: "memory");

    // wait until both halves of y rows [tc*128, tc*128+128) are published
    if (threadIdx.x == 0) {
        const int need = (tc + 1) * 128;
        while (*(volatile int*)&g_progA[b] < need ||
               *(volatile int*)&g_progB[b] < need)
            __nanosleep(512);
    }
    __syncthreads();

    const int tid = threadIdx.x;
    const int tx = tid & 15;
    const int ty = tid >> 4;
    const int lrow = tid & 127;
    const int lk = tid >> 7;

    unsigned long long acc[8][4];
#pragma unroll
    for (int i = 0; i < 8; i++)
#pragma unroll
        for (int j = 0; j < 4; j++) acc[i][j] = 0ull;

    const float* Y = g_y;

    for (int kc = 0; kc < RD; kc += HBK) {
        __syncthreads();
#pragma unroll
        for (int i = 0; i < 4; i++) {
            int kq = lk + 2 * i;
            float4 a = *(const float4*)(Y + (size_t)(m0 + lrow) * RD + kc + kq * 4);
            As[kq * 4 + 0][lrow] = a.x;
            As[kq * 4 + 1][lrow] = a.y;
            As[kq * 4 + 2][lrow] = a.z;
            As[kq * 4 + 3][lrow] = a.w;
            float4 bv = *(const float4*)(E + (size_t)(n0 + lrow) * RD + kc + kq * 4);
            Bs[kq * 4 + 0][lrow] = bv.x;
            Bs[kq * 4 + 1][lrow] = bv.y;
            Bs[kq * 4 + 2][lrow] = bv.z;
            Bs[kq * 4 + 3][lrow] = bv.w;
        }
        __syncthreads();

#pragma unroll
        for (int k = 0; k < HBK; k++) {
            float4 a0 = *(const float4*)&As[k][ty * 8];
            float4 a1 = *(const float4*)&As[k][ty * 8 + 4];
            ulonglong2 b0 = *(const ulonglong2*)&Bs[k][tx * 8];
            ulonglong2 b1 = *(const ulonglong2*)&Bs[k][tx * 8 + 4];
            float av[8] = {a0.x, a0.y, a0.z, a0.w, a1.x, a1.y, a1.z, a1.w};
#pragma unroll
            for (int i = 0; i < 8; i++) {
                unsigned long long as = pack2(av[i], av[i]);
                fma2(acc[i][0], as, b0.x);
                fma2(acc[i][1], as, b0.y);
                fma2(acc[i][2], as, b1.x);
                fma2(acc[i][3], as, b1.y);
            }
        }
    }

#pragma unroll
    for (int i = 0; i < 8; i++) {
        size_t row = (size_t)(m0 + ty * 8 + i);
        float2 c0 = unpack2(acc[i][0]);
        float2 c1 = unpack2(acc[i][1]);
        float2 c2 = unpack2(acc[i][2]);
        float2 c3 = unpack2(acc[i][3]);
        *(float4*)(out + row * RV + n0 + tx * 8) = make_float4(c0.x, c0.y, c1.x, c1.y);
        *(float4*)(out + row * RV + n0 + tx * 8 + 4) = make_float4(c2.x, c2.y, c3.x, c3.y);
    }
}

// ============================================================================
extern "C" void kernel_launch(void* const* d_in, const int* in_sizes, int n_in,
                              void* d_out, int out_size) {
    const int* tokens = (const int*)d_in[0];
    const float* E = (const float*)d_in[1];
    const float* Wx = (const float*)d_in[2];
    const float* Wh = (const float*)d_in[3];
    const float* Wz = (const float*)d_in[4];
    float* out = (float*)d_out;

    (void)in_sizes; (void)n_in; (void)out_size;

    rnn_tables_kernel<<<RV, RD>>>(E, Wx, Wz);

    rnn_recurrence_kernel<<<RB * 2, 512>>>(tokens, Wh);

    // K3 with programmatic stream serialization: may start while K2 runs.
    cudaLaunchConfig_t cfg = {};
    cfg.gridDim = dim3(2048, 1, 1);
    cfg.blockDim = dim3(256, 1, 1);
    cfg.dynamicSmemBytes = 0;
    cfg.stream = 0;
    cudaLaunchAttribute attrs[1];
    attrs[0].id = cudaLaunchAttributeProgrammaticStreamSerialization;
    attrs[0].val.programmaticStreamSerializationAllowed = 1;
    cfg.attrs = attrs;
    cfg.numAttrs = 1;
    cudaLaunchKernelEx(&cfg, rnn_head_kernel, E, out);
}